// round 14
// baseline (speedup 1.0000x reference)
#include <cuda_runtime.h>
#include <cuda_fp16.h>
#include <stdint.h>

#define DIM 4096
#define NHEADS 32
#define HD 128
#define BSZ 4
#define SEQ 512
#define MAXSEQ 2048

// ---------------- scratch ----------------
static __device__ __align__(256) __half g_xh[(size_t)BSZ * SEQ * DIM];
static __device__ __align__(256) __half g_attnh[(size_t)BSZ * SEQ * DIM];
static __device__ __align__(256) __half g_wh[(size_t)4 * DIM * DIM];
static __device__ __align__(256) __half g_qh[(size_t)BSZ * SEQ * DIM];
static __device__ __align__(256) __half g_kh[(size_t)BSZ * SEQ * DIM];
static __device__ __align__(256) __half g_vh[(size_t)BSZ * SEQ * DIM];

// ---------------- helpers ----------------
__device__ __forceinline__ uint32_t smem_u32(const void* p) {
    uint32_t r;
    asm("{ .reg .u64 t; cvta.to.shared.u64 t, %1; cvt.u32.u64 %0, t; }" : "=r"(r) : "l"(p));
    return r;
}

__device__ __forceinline__ void cp16(uint32_t d, const void* g) {
    asm volatile("cp.async.cg.shared.global [%0], [%1], 16;" :: "r"(d), "l"(g) : "memory");
}
#define CP_COMMIT() asm volatile("cp.async.commit_group;" ::: "memory")
#define CP_WAIT1()  asm volatile("cp.async.wait_group 1;" ::: "memory")
#define CP_WAIT0()  asm volatile("cp.async.wait_group 0;" ::: "memory")

__device__ __forceinline__ void ldsm4(uint32_t* r, uint32_t a) {
    asm volatile("ldmatrix.sync.aligned.m8n8.x4.shared.b16 {%0,%1,%2,%3}, [%4];"
                 : "=r"(r[0]), "=r"(r[1]), "=r"(r[2]), "=r"(r[3]) : "r"(a));
}
__device__ __forceinline__ void ldsm4t(uint32_t* r, uint32_t a) {
    asm volatile("ldmatrix.sync.aligned.m8n8.x4.trans.shared.b16 {%0,%1,%2,%3}, [%4];"
                 : "=r"(r[0]), "=r"(r[1]), "=r"(r[2]), "=r"(r[3]) : "r"(a));
}

__device__ __forceinline__ void mma_16816(float* c, const uint32_t* a, const uint32_t* b) {
    asm volatile(
        "mma.sync.aligned.m16n8k16.row.col.f32.f16.f16.f32 "
        "{%0,%1,%2,%3}, {%4,%5,%6,%7}, {%8,%9}, {%0,%1,%2,%3};\n"
        : "+f"(c[0]), "+f"(c[1]), "+f"(c[2]), "+f"(c[3])
        : "r"(a[0]), "r"(a[1]), "r"(a[2]), "r"(a[3]),
          "r"(b[0]), "r"(b[1]));
}

__device__ __forceinline__ uint32_t pack2f(float a, float b) {
    __half2 t = __floats2half2_rn(a, b);
    return *reinterpret_cast<uint32_t*>(&t);
}

constexpr float QK_SCALE = 0.08838834764831845f;  // 1/sqrt(128)

// =====================================================================
//  gemm64n: CTA tile 128x64, 256 threads (8 warps), warp tile 32x32,
//  BK=64, 2-stage cp.async ring, 3 CTAs/SM.
//  Epilogue mode: 0=Q(rope->fp16 qh), 1=K(rope->fp16 kh + fp32 cacheK),
//                 2=V(fp16 vh + fp32 cacheV), 3=plain fp32 C.
//  blockIdx.z == 3 (QKV launch only): cache-tail zeroing filler blocks.
// =====================================================================
constexpr int GP = 72;                        // smem pitch (halves)
constexpr int GA_ST = 128 * GP;               // A stage halves
constexpr int GB_ST = 64 * GP;                // B stage halves
constexpr int G_SMEM = 2 * (GA_ST + GB_ST) * 2;  // 55296 bytes

struct GemmSet {
    const __half* B[3];
    const float*  s[3];
    float*        C[3];      // mode 3: output; modes 1/2: cache base
    int           mode[3];
};

__global__ void __launch_bounds__(256, 3) gemm64n(
    const __half* __restrict__ A, GemmSet gs,
    const float* __restrict__ fcos, const float* __restrict__ fsin,
    const int* __restrict__ idx)
{
    // ---- filler blocks: zero cache tails (rows 512..2047 of both caches) ----
    if (blockIdx.z == 3) {
        float4* ck = (float4*)gs.C[1];
        float4* cv = (float4*)gs.C[2];
        const int perB = 1536 * 1024;            // float4 per batch tail
        const int n = BSZ * perB;
        const float4 z4 = make_float4(0.f, 0.f, 0.f, 0.f);
        const int nb = gridDim.x * gridDim.y;
        const int bid = blockIdx.y * gridDim.x + blockIdx.x;
        for (int i = bid * 256 + threadIdx.x; i < n; i += nb * 256) {
            const int b = i / perB, r = i - b * perB;
            const size_t off = ((size_t)b * MAXSEQ + SEQ) * (DIM / 4) + r;
            ck[off] = z4;
            cv[off] = z4;
        }
        return;
    }

    extern __shared__ __half sm[];
    __half* As = sm;                 // [2][128][72]
    __half* Bs = sm + 2 * GA_ST;     // [2][64][72]

    const __half* Bw = gs.B[blockIdx.z];
    const float*  scale = gs.s[blockIdx.z];
    float*        C = gs.C[blockIdx.z];
    const int     mode = gs.mode[blockIdx.z];

    const int K = DIM;
    const int tid = threadIdx.x;
    const int warp = tid >> 5, lane = tid & 31;
    const int m0 = blockIdx.y * 128, n0 = blockIdx.x * 64;
    const int wm = (warp & 3) * 32, wn = (warp >> 2) * 32;
    const int gid = lane >> 2, t2 = (lane & 3) * 2;

    // ---- loaders: A 1024 chunks (4/thread), B 512 chunks (2/thread) ----
    uint32_t aD[4], bD[2];
    const __half *Ag[4], *Bg[2];
#pragma unroll
    for (int j = 0; j < 4; j++) {
        const int id = tid + j * 256;
        const int row = id >> 3, sub = (id & 7) * 8;
        aD[j] = smem_u32(As + row * GP + sub);
        Ag[j] = A + (size_t)(m0 + row) * K + sub;
    }
#pragma unroll
    for (int j = 0; j < 2; j++) {
        const int id = tid + j * 256;
        const int row = id >> 3, sub = (id & 7) * 8;
        bD[j] = smem_u32(Bs + row * GP + sub);
        Bg[j] = Bw + (size_t)(n0 + row) * K + sub;
    }

    // ---- fragment lane addressing ----
    const int a_r = (lane & 7) + ((lane >> 3) & 1) * 8;
    const int a_c = ((lane >> 4) & 1) * 8;
    const int b_r = (lane & 7) + ((lane >> 4) & 1) * 8;
    const int b_c = ((lane >> 3) & 1) * 8;
    const uint32_t aF0 = smem_u32(As + (wm + a_r) * GP + a_c);
    const uint32_t bF0 = smem_u32(Bs + (wn + b_r) * GP + b_c);

    float c[2][4][4];
#pragma unroll
    for (int mt = 0; mt < 2; mt++)
#pragma unroll
        for (int nt = 0; nt < 4; nt++)
#pragma unroll
            for (int r = 0; r < 4; r++) c[mt][nt][r] = 0.f;

    // ---- prologue ----
#pragma unroll
    for (int s = 0; s < 2; s++) {
#pragma unroll
        for (int j = 0; j < 4; j++)
            cp16(aD[j] + (uint32_t)(s * GA_ST * 2), Ag[j] + s * 64);
#pragma unroll
        for (int j = 0; j < 2; j++)
            cp16(bD[j] + (uint32_t)(s * GB_ST * 2), Bg[j] + s * 64);
        CP_COMMIT();
    }

    const int NK = K / 64;  // 64
    for (int kt = 0; kt < NK; kt++) {
        const int s = kt & 1;
        CP_WAIT1();
        __syncthreads();

        const uint32_t aB = aF0 + (uint32_t)(s * GA_ST * 2);
        const uint32_t bB = bF0 + (uint32_t)(s * GB_ST * 2);
#pragma unroll
        for (int kk = 0; kk < 64; kk += 16) {
            uint32_t af[2][4], bf[2][4];
#pragma unroll
            for (int mt = 0; mt < 2; mt++)
                ldsm4(af[mt], aB + (mt * 16 * GP + kk) * 2);
#pragma unroll
            for (int p = 0; p < 2; p++)
                ldsm4(bf[p], bB + (p * 16 * GP + kk) * 2);
#pragma unroll
            for (int mt = 0; mt < 2; mt++)
#pragma unroll
                for (int nt = 0; nt < 4; nt++)
                    mma_16816(c[mt][nt], af[mt], &bf[nt >> 1][(nt & 1) * 2]);
        }
        __syncthreads();

        if (kt + 2 < NK) {
            const int ko = (kt + 2) * 64;
#pragma unroll
            for (int j = 0; j < 4; j++)
                cp16(aD[j] + (uint32_t)(s * GA_ST * 2), Ag[j] + ko);
#pragma unroll
            for (int j = 0; j < 2; j++)
                cp16(bD[j] + (uint32_t)(s * GB_ST * 2), Bg[j] + ko);
        }
        CP_COMMIT();
    }

    // ---- epilogue ----
    if (mode == 3) {
#pragma unroll
        for (int nt = 0; nt < 4; nt++) {
            const int col = n0 + wn + nt * 8 + t2;
            const float s0 = __ldg(scale + col), s1 = __ldg(scale + col + 1);
#pragma unroll
            for (int mt = 0; mt < 2; mt++) {
                const int row = m0 + wm + mt * 16 + gid;
                C[(size_t)row * DIM + col]           = c[mt][nt][0] * s0;
                C[(size_t)row * DIM + col + 1]       = c[mt][nt][1] * s1;
                C[(size_t)(row + 8) * DIM + col]     = c[mt][nt][2] * s0;
                C[(size_t)(row + 8) * DIM + col + 1] = c[mt][nt][3] * s1;
            }
        }
        return;
    }

    const int row0 = m0 + wm + gid;
#pragma unroll
    for (int mt = 0; mt < 2; mt++) {
#pragma unroll
        for (int half = 0; half < 2; half++) {
            const int row = row0 + mt * 16 + half * 8;
            const int sq = row & 511, b = row >> 9;
            __half* outH;
            float* cacheRow = nullptr;
            if (mode == 0) {
                outH = g_qh + (size_t)row * DIM;
            } else if (mode == 1) {
                outH = g_kh + (size_t)row * DIM;
                cacheRow = C + ((size_t)(b * MAXSEQ + __ldg(idx + sq))) * DIM;
            } else {
                outH = g_vh + (size_t)row * DIM;
                cacheRow = C + ((size_t)(b * MAXSEQ + __ldg(idx + sq))) * DIM;
            }
#pragma unroll
            for (int nt = 0; nt < 4; nt++) {
                const int col = n0 + wn + nt * 8 + t2;
                const float s0 = __ldg(scale + col), s1 = __ldg(scale + col + 1);
                const float v0 = c[mt][nt][half * 2]     * s0;
                const float v1 = c[mt][nt][half * 2 + 1] * s1;
                if (mode == 2) {
                    *(uint32_t*)(outH + col) = pack2f(v0, v1);
                    float2 f2; f2.x = v0; f2.y = v1;
                    *(float2*)(cacheRow + col) = f2;
                } else {
                    const int p = (col & 127) >> 1;
                    const float cv = __ldg(fcos + sq * 64 + p);
                    const float sv = __ldg(fsin + sq * 64 + p);
                    const float r0 = v0 * cv - v1 * sv;
                    const float r1 = v0 * sv + v1 * cv;
                    if (mode == 0) {
                        *(uint32_t*)(outH + col) = pack2f(r0 * QK_SCALE, r1 * QK_SCALE);
                    } else {
                        *(uint32_t*)(outH + col) = pack2f(r0, r1);
                        float2 f2; f2.x = r0; f2.y = r1;
                        *(float2*)(cacheRow + col) = f2;
                    }
                }
            }
        }
    }
}

// =====================================================================
// prep kernel: y=0..2 weights wq/wk/wv int32->fp16; y=3 x fp32->fp16
// (wo conversion is folded into the flash launch's idle tail)
// =====================================================================
struct WSet { const int4* w[3]; __half* o[3]; };

__global__ void prep_kernel(WSet ws, const float4* __restrict__ x,
                            __half* __restrict__ xout, int wN4, int xN4)
{
    if (blockIdx.y < 3) {
        const int4* w = ws.w[blockIdx.y];
        __half* out = ws.o[blockIdx.y];
        for (int i = blockIdx.x * blockDim.x + threadIdx.x; i < wN4; i += gridDim.x * blockDim.x) {
            const int4 v = w[i];
            __half2 h0 = __halves2half2(__int2half_rn(v.x), __int2half_rn(v.y));
            __half2 h1 = __halves2half2(__int2half_rn(v.z), __int2half_rn(v.w));
            uint2 u;
            u.x = *reinterpret_cast<uint32_t*>(&h0);
            u.y = *reinterpret_cast<uint32_t*>(&h1);
            ((uint2*)out)[i] = u;
        }
    } else {
        for (int i = blockIdx.x * blockDim.x + threadIdx.x; i < xN4; i += gridDim.x * blockDim.x) {
            const float4 v = x[i];
            __half2 h0 = __floats2half2_rn(v.x, v.y);
            __half2 h1 = __floats2half2_rn(v.z, v.w);
            uint2 u;
            u.x = *reinterpret_cast<uint32_t*>(&h0);
            u.y = *reinterpret_cast<uint32_t*>(&h1);
            ((uint2*)xout)[i] = u;
        }
    }
}

// =====================================================================
// Flash attention. grid (128, 6): y in [0,4) attention (qt = 3-y, LPT),
// y in [4,6) = wo int32->fp16 conversion filler blocks.
// =====================================================================
constexpr int FP = 136;
constexpr int F_TILE = 128 * FP;
constexpr int F_SMEM = 5 * F_TILE * 2;

__global__ __launch_bounds__(256) void flash_kernel(
    const int4* __restrict__ woSrc, __half* __restrict__ woDst, int wN4)
{
    if (blockIdx.y >= 4) {
        const int bid = (blockIdx.y - 4) * gridDim.x + blockIdx.x;  // 0..255
        for (int i = bid * 256 + threadIdx.x; i < wN4; i += 256 * 256) {
            const int4 v = woSrc[i];
            __half2 h0 = __halves2half2(__int2half_rn(v.x), __int2half_rn(v.y));
            __half2 h1 = __halves2half2(__int2half_rn(v.z), __int2half_rn(v.w));
            uint2 u;
            u.x = *reinterpret_cast<uint32_t*>(&h0);
            u.y = *reinterpret_cast<uint32_t*>(&h1);
            ((uint2*)woDst)[i] = u;
        }
        return;
    }

    extern __shared__ __half sm[];
    __half* Qs = sm;
    __half* Ks = sm + F_TILE;
    __half* Vs = sm + 3 * F_TILE;

    const int qt = 3 - blockIdx.y;    // LPT: heaviest tiles first
    const int z  = blockIdx.x;
    const int b = z >> 5, h = z & 31;
    const int tid = threadIdx.x, warp = tid >> 5, lane = tid & 31;
    const int gid = lane >> 2, t2 = (lane & 3) * 2;

    const __half* Qg = g_qh + ((size_t)(b * SEQ + qt * 128)) * DIM + h * HD;
    const __half* Kg = g_kh + ((size_t)b * SEQ) * DIM + h * HD;
    const __half* Vg = g_vh + ((size_t)b * SEQ) * DIM + h * HD;

#pragma unroll
    for (int j = 0; j < 8; j++) {
        const int c = tid + j * 256;
        const int row = c >> 4, sub = (c & 15) * 8;
        cp16(smem_u32(Qs + row * FP + sub), Qg + (size_t)row * DIM + sub);
    }
    CP_COMMIT();
#pragma unroll
    for (int j = 0; j < 8; j++) {
        const int c = tid + j * 256;
        const int row = c >> 4, sub = (c & 15) * 8;
        cp16(smem_u32(Ks + row * FP + sub), Kg + (size_t)row * DIM + sub);
        cp16(smem_u32(Vs + row * FP + sub), Vg + (size_t)row * DIM + sub);
    }
    CP_COMMIT();
    CP_WAIT0();
    __syncthreads();

    const int fr = (lane & 7) + ((lane >> 3) & 1) * 8;
    const int fc = ((lane >> 4) & 1) * 8;
    const int kb_r = (lane & 7) + ((lane >> 4) & 1) * 8;
    const int kb_c = ((lane >> 3) & 1) * 8;

    const uint32_t qB = smem_u32(Qs + (warp * 16 + fr) * FP + fc);

    float o[16][4];
#pragma unroll
    for (int nt = 0; nt < 16; nt++)
#pragma unroll
        for (int r = 0; r < 4; r++) o[nt][r] = 0.f;
    float m0 = -1e30f, m1 = -1e30f, l0 = 0.f, l1 = 0.f;

    for (int kt = 0; kt <= qt; kt++) {
        const int buf = kt & 1;

        if (kt < qt) {
            const __half* Kn = Kg + (size_t)(kt + 1) * 128 * DIM;
            const __half* Vn = Vg + (size_t)(kt + 1) * 128 * DIM;
            __half* Kd = Ks + (buf ^ 1) * F_TILE;
            __half* Vd = Vs + (buf ^ 1) * F_TILE;
#pragma unroll
            for (int j = 0; j < 8; j++) {
                const int c = tid + j * 256;
                const int row = c >> 4, sub = (c & 15) * 8;
                cp16(smem_u32(Kd + row * FP + sub), Kn + (size_t)row * DIM + sub);
                cp16(smem_u32(Vd + row * FP + sub), Vn + (size_t)row * DIM + sub);
            }
            CP_COMMIT();
        }

        const uint32_t kB = smem_u32(Ks + buf * F_TILE + kb_r * FP + kb_c);
        const uint32_t vB = smem_u32(Vs + buf * F_TILE + fr * FP + fc);

        float s[16][4];
#pragma unroll
        for (int nt = 0; nt < 16; nt++)
#pragma unroll
            for (int r = 0; r < 4; r++) s[nt][r] = 0.f;

#pragma unroll
        for (int kk = 0; kk < 8; kk++) {
            uint32_t a[4];
            ldsm4(a, qB + kk * 32);
#pragma unroll
            for (int p = 0; p < 8; p++) {
                uint32_t bk[4];
                ldsm4(bk, kB + (p * 16 * FP + kk * 16) * 2);
                mma_16816(s[2 * p],     a, bk);
                mma_16816(s[2 * p + 1], a, bk + 2);
            }
        }

        if (kt == qt) {
            const int r0 = warp * 16 + gid, r1 = r0 + 8;
#pragma unroll
            for (int nt = 0; nt < 16; nt++) {
                const int c0 = nt * 8 + t2;
                if (c0 > r0)     s[nt][0] = -1e30f;
                if (c0 + 1 > r0) s[nt][1] = -1e30f;
                if (c0 > r1)     s[nt][2] = -1e30f;
                if (c0 + 1 > r1) s[nt][3] = -1e30f;
            }
        }

        float mx0 = -1e30f, mx1 = -1e30f;
#pragma unroll
        for (int nt = 0; nt < 16; nt++) {
            mx0 = fmaxf(mx0, fmaxf(s[nt][0], s[nt][1]));
            mx1 = fmaxf(mx1, fmaxf(s[nt][2], s[nt][3]));
        }
        mx0 = fmaxf(mx0, __shfl_xor_sync(0xffffffffu, mx0, 1));
        mx0 = fmaxf(mx0, __shfl_xor_sync(0xffffffffu, mx0, 2));
        mx1 = fmaxf(mx1, __shfl_xor_sync(0xffffffffu, mx1, 1));
        mx1 = fmaxf(mx1, __shfl_xor_sync(0xffffffffu, mx1, 2));

        const float mn0 = fmaxf(m0, mx0), mn1 = fmaxf(m1, mx1);
        const float sc0 = __expf(m0 - mn0), sc1 = __expf(m1 - mn1);
        m0 = mn0; m1 = mn1;

        float sum0 = 0.f, sum1 = 0.f;
#pragma unroll
        for (int nt = 0; nt < 16; nt++) {
            s[nt][0] = __expf(s[nt][0] - mn0);
            s[nt][1] = __expf(s[nt][1] - mn0);
            s[nt][2] = __expf(s[nt][2] - mn1);
            s[nt][3] = __expf(s[nt][3] - mn1);
            sum0 += s[nt][0] + s[nt][1];
            sum1 += s[nt][2] + s[nt][3];
        }
        sum0 += __shfl_xor_sync(0xffffffffu, sum0, 1);
        sum0 += __shfl_xor_sync(0xffffffffu, sum0, 2);
        sum1 += __shfl_xor_sync(0xffffffffu, sum1, 1);
        sum1 += __shfl_xor_sync(0xffffffffu, sum1, 2);
        l0 = l0 * sc0 + sum0;
        l1 = l1 * sc1 + sum1;

#pragma unroll
        for (int nt = 0; nt < 16; nt++) {
            o[nt][0] *= sc0; o[nt][1] *= sc0;
            o[nt][2] *= sc1; o[nt][3] *= sc1;
        }

#pragma unroll
        for (int ks = 0; ks < 8; ks++) {
            uint32_t pa[4];
            pa[0] = pack2f(s[2 * ks][0],     s[2 * ks][1]);
            pa[1] = pack2f(s[2 * ks][2],     s[2 * ks][3]);
            pa[2] = pack2f(s[2 * ks + 1][0], s[2 * ks + 1][1]);
            pa[3] = pack2f(s[2 * ks + 1][2], s[2 * ks + 1][3]);
#pragma unroll
            for (int dp = 0; dp < 8; dp++) {
                uint32_t vb[4];
                ldsm4t(vb, vB + (ks * 16 * FP + dp * 16) * 2);
                mma_16816(o[2 * dp],     pa, vb);
                mma_16816(o[2 * dp + 1], pa, vb + 2);
            }
        }

        if (kt < qt) {
            CP_WAIT0();
            __syncthreads();
        }
    }

    const float i0 = 1.f / l0, i1 = 1.f / l1;
    const int r0 = qt * 128 + warp * 16 + gid;
    __half* O0 = g_attnh + (size_t)(b * SEQ + r0) * DIM + h * HD;
    __half* O1 = O0 + (size_t)8 * DIM;
#pragma unroll
    for (int nt = 0; nt < 16; nt++) {
        const int col = nt * 8 + t2;
        *(uint32_t*)(O0 + col) = pack2f(o[nt][0] * i0, o[nt][1] * i0);
        *(uint32_t*)(O1 + col) = pack2f(o[nt][2] * i1, o[nt][3] * i1);
    }
}

// =====================================================================
extern "C" void kernel_launch(void* const* d_in, const int* in_sizes, int n_in,
                              void* d_out, int out_size)
{
    (void)in_sizes; (void)n_in; (void)out_size;
    const float* x    = (const float*)d_in[0];
    const float* fcos = (const float*)d_in[1];
    const float* fsin = (const float*)d_in[2];
    const int*   idx  = (const int*)d_in[4];
    const int*   wq   = (const int*)d_in[7];
    const float* sq   = (const float*)d_in[8];
    const int*   wk   = (const int*)d_in[9];
    const float* sk   = (const float*)d_in[10];
    const int*   wv   = (const int*)d_in[11];
    const float* sv   = (const float*)d_in[12];
    const int*   wo   = (const int*)d_in[13];
    const float* so   = (const float*)d_in[14];

    float* out    = (float*)d_out;
    float* cacheK = out + (size_t)BSZ * SEQ * DIM;
    float* cacheV = cacheK + (size_t)BSZ * MAXSEQ * NHEADS * HD;

    __half *pxh = nullptr, *pwh = nullptr, *pah = nullptr;
    cudaGetSymbolAddress((void**)&pxh, g_xh);
    cudaGetSymbolAddress((void**)&pwh, g_wh);
    cudaGetSymbolAddress((void**)&pah, g_attnh);

    cudaFuncSetAttribute(gemm64n, cudaFuncAttributeMaxDynamicSharedMemorySize, G_SMEM);
    cudaFuncSetAttribute(flash_kernel, cudaFuncAttributeMaxDynamicSharedMemorySize, F_SMEM);

    const size_t W = (size_t)DIM * DIM;

    // 1) conversions (wq, wk, wv, x) — wo deferred into the flash launch
    WSet ws;
    ws.w[0] = (const int4*)wq; ws.o[0] = pwh + 0 * W;
    ws.w[1] = (const int4*)wk; ws.o[1] = pwh + 1 * W;
    ws.w[2] = (const int4*)wv; ws.o[2] = pwh + 2 * W;
    prep_kernel<<<dim3(1184, 4), 256>>>(ws, (const float4*)x, pxh,
                                        (int)(W / 4), (int)(BSZ * SEQ * DIM / 4));

    // 2) fused QKV projection + RoPE + cache scatter; z=3 = tail-zero filler
    GemmSet qkv;
    qkv.B[0] = pwh + 0 * W; qkv.s[0] = sq; qkv.C[0] = nullptr; qkv.mode[0] = 0;
    qkv.B[1] = pwh + 1 * W; qkv.s[1] = sk; qkv.C[1] = cacheK;  qkv.mode[1] = 1;
    qkv.B[2] = pwh + 2 * W; qkv.s[2] = sv; qkv.C[2] = cacheV;  qkv.mode[2] = 2;
    gemm64n<<<dim3(DIM / 64, (BSZ * SEQ) / 128, 4), 256, G_SMEM>>>(pxh, qkv, fcos, fsin, idx);

    // 3) fused flash attention (heavy tiles first) + wo-conversion filler
    flash_kernel<<<dim3(BSZ * NHEADS, 6), 256, F_SMEM>>>(
        (const int4*)wo, pwh + 3 * W, (int)(W / 4));

    // 4) output projection
    GemmSet og;
    og.B[0] = pwh + 3 * W; og.s[0] = so; og.C[0] = out; og.mode[0] = 3;
    og.B[1] = og.B[0]; og.s[1] = og.s[0]; og.C[1] = og.C[0]; og.mode[1] = 3;
    og.B[2] = og.B[0]; og.s[2] = og.s[0]; og.C[2] = og.C[0]; og.mode[2] = 3;
    gemm64n<<<dim3(DIM / 64, (BSZ * SEQ) / 128, 1), 256, G_SMEM>>>(pah, og, fcos, fsin, idx);
}

// round 15
// speedup vs baseline: 1.1164x; 1.1164x over previous
#include <cuda_runtime.h>
#include <cuda_fp16.h>
#include <stdint.h>

#define DIM 4096
#define NHEADS 32
#define HD 128
#define BSZ 4
#define SEQ 512
#define MAXSEQ 2048

// ---------------- scratch ----------------
static __device__ __align__(256) __half g_xh[(size_t)BSZ * SEQ * DIM];
static __device__ __align__(256) __half g_attnh[(size_t)BSZ * SEQ * DIM];
static __device__ __align__(256) __half g_wh[(size_t)4 * DIM * DIM];
static __device__ __align__(256) __half g_qh[(size_t)BSZ * SEQ * DIM];
static __device__ __align__(256) __half g_kh[(size_t)BSZ * SEQ * DIM];
static __device__ __align__(256) __half g_vh[(size_t)BSZ * SEQ * DIM];

// ---------------- helpers ----------------
__device__ __forceinline__ uint32_t smem_u32(const void* p) {
    uint32_t r;
    asm("{ .reg .u64 t; cvta.to.shared.u64 t, %1; cvt.u32.u64 %0, t; }" : "=r"(r) : "l"(p));
    return r;
}

__device__ __forceinline__ void cp16(uint32_t d, const void* g) {
    asm volatile("cp.async.cg.shared.global [%0], [%1], 16;" :: "r"(d), "l"(g) : "memory");
}
#define CP_COMMIT() asm volatile("cp.async.commit_group;" ::: "memory")
#define CP_WAIT1()  asm volatile("cp.async.wait_group 1;" ::: "memory")
#define CP_WAIT0()  asm volatile("cp.async.wait_group 0;" ::: "memory")

__device__ __forceinline__ void ldsm4(uint32_t* r, uint32_t a) {
    asm volatile("ldmatrix.sync.aligned.m8n8.x4.shared.b16 {%0,%1,%2,%3}, [%4];"
                 : "=r"(r[0]), "=r"(r[1]), "=r"(r[2]), "=r"(r[3]) : "r"(a));
}
__device__ __forceinline__ void ldsm4t(uint32_t* r, uint32_t a) {
    asm volatile("ldmatrix.sync.aligned.m8n8.x4.trans.shared.b16 {%0,%1,%2,%3}, [%4];"
                 : "=r"(r[0]), "=r"(r[1]), "=r"(r[2]), "=r"(r[3]) : "r"(a));
}

__device__ __forceinline__ void mma_16816(float* c, const uint32_t* a, const uint32_t* b) {
    asm volatile(
        "mma.sync.aligned.m16n8k16.row.col.f32.f16.f16.f32 "
        "{%0,%1,%2,%3}, {%4,%5,%6,%7}, {%8,%9}, {%0,%1,%2,%3};\n"
        : "+f"(c[0]), "+f"(c[1]), "+f"(c[2]), "+f"(c[3])
        : "r"(a[0]), "r"(a[1]), "r"(a[2]), "r"(a[3]),
          "r"(b[0]), "r"(b[1]));
}

__device__ __forceinline__ uint32_t pack2f(float a, float b) {
    __half2 t = __floats2half2_rn(a, b);
    return *reinterpret_cast<uint32_t*>(&t);
}

constexpr float QK_SCALE = 0.08838834764831845f;  // 1/sqrt(128)

// =====================================================================
//  gemm128: CTA tile 128x128, 256 threads, warp tile 32x64, BK=64,
//  2-stage cp.async ring, 2 CTAs/SM  (proven round-12 mainloop).
//  z <  nGemm           : GEMM slice (mode 0=Q rope, 1=K rope+cache,
//                          2=V+cache, 3=plain fp32)
//  z in [nGemm,+nConv)  : filler — int32 weight -> fp16 conversion
//  z == nGemm+nConv     : filler — cache tail zeroing
// =====================================================================
constexpr int GP = 72;                       // smem pitch (halves)
constexpr int G_ST = 128 * GP;               // per-matrix stage halves
constexpr int G_SMEM = 2 * 2 * G_ST * 2;     // 73728 bytes

struct GemmSet {
    const __half* B[2];
    const float*  s[2];
    float*        C[2];      // mode 3: output; modes 1/2: cache base
    int           mode[2];
    int           nGemm;
    int           nConv;
    const int4*   cw[2];     // conversion filler sources
    __half*       cwo[2];    // conversion filler dests
    int           wN4;
    float*        zk;        // zero-tail targets
    float*        zv;
};

__global__ void __launch_bounds__(256, 2) gemm128(
    const __half* __restrict__ A, GemmSet gs,
    const float* __restrict__ fcos, const float* __restrict__ fsin,
    const int* __restrict__ idx)
{
    if ((int)blockIdx.z >= gs.nGemm) {
        const int f = (int)blockIdx.z - gs.nGemm;
        const int bid = blockIdx.y * gridDim.x + blockIdx.x;
        const int nb = gridDim.x * gridDim.y;
        if (f < gs.nConv) {
            // ---- filler: convert one int32 weight matrix to fp16 ----
            const int4* w = gs.cw[f];
            __half* o = gs.cwo[f];
            for (int i = bid * 256 + threadIdx.x; i < gs.wN4; i += nb * 256) {
                const int4 v = w[i];
                __half2 h0 = __halves2half2(__int2half_rn(v.x), __int2half_rn(v.y));
                __half2 h1 = __halves2half2(__int2half_rn(v.z), __int2half_rn(v.w));
                uint2 u;
                u.x = *reinterpret_cast<uint32_t*>(&h0);
                u.y = *reinterpret_cast<uint32_t*>(&h1);
                ((uint2*)o)[i] = u;
            }
            return;
        }
        // ---- filler: zero cache tails (rows 512..2047) ----
        float4* ck = (float4*)gs.zk;
        float4* cv = (float4*)gs.zv;
        const int perB = 1536 * 1024;
        const int n = BSZ * perB;
        const float4 z4 = make_float4(0.f, 0.f, 0.f, 0.f);
        for (int i = bid * 256 + threadIdx.x; i < n; i += nb * 256) {
            const int b = i / perB, r = i - b * perB;
            const size_t off = ((size_t)b * MAXSEQ + SEQ) * (DIM / 4) + r;
            ck[off] = z4;
            cv[off] = z4;
        }
        return;
    }

    extern __shared__ __half sm[];
    __half* As = sm;                 // [2][128][72]
    __half* Bs = sm + 2 * G_ST;      // [2][128][72]

    const __half* Bw = gs.B[blockIdx.z];
    const float*  scale = gs.s[blockIdx.z];
    float*        C = gs.C[blockIdx.z];
    const int     mode = gs.mode[blockIdx.z];

    const int K = DIM;
    const int tid = threadIdx.x;
    const int warp = tid >> 5, lane = tid & 31;
    const int m0 = blockIdx.y * 128, n0 = blockIdx.x * 128;
    const int wm = (warp & 3) * 32, wn = (warp >> 2) * 64;
    const int gid = lane >> 2, t2 = (lane & 3) * 2;

    // ---- loaders ----
    uint32_t aD[4], bD[4];
    const __half *Ag[4], *Bg[4];
#pragma unroll
    for (int j = 0; j < 4; j++) {
        const int id = tid + j * 256;
        const int row = id >> 3, sub = (id & 7) * 8;
        aD[j] = smem_u32(As + row * GP + sub);
        bD[j] = smem_u32(Bs + row * GP + sub);
        Ag[j] = A + (size_t)(m0 + row) * K + sub;
        Bg[j] = Bw + (size_t)(n0 + row) * K + sub;
    }

    // ---- fragment lane addressing ----
    const int a_r = (lane & 7) + ((lane >> 3) & 1) * 8;
    const int a_c = ((lane >> 4) & 1) * 8;
    const int b_r = (lane & 7) + ((lane >> 4) & 1) * 8;
    const int b_c = ((lane >> 3) & 1) * 8;
    const uint32_t aF0 = smem_u32(As + (wm + a_r) * GP + a_c);
    const uint32_t bF0 = smem_u32(Bs + (wn + b_r) * GP + b_c);

    float c[2][8][4];
#pragma unroll
    for (int mt = 0; mt < 2; mt++)
#pragma unroll
        for (int nt = 0; nt < 8; nt++)
#pragma unroll
            for (int r = 0; r < 4; r++) c[mt][nt][r] = 0.f;

    // ---- prologue ----
#pragma unroll
    for (int s = 0; s < 2; s++) {
#pragma unroll
        for (int j = 0; j < 4; j++) {
            cp16(aD[j] + (uint32_t)(s * G_ST * 2), Ag[j] + s * 64);
            cp16(bD[j] + (uint32_t)(s * G_ST * 2), Bg[j] + s * 64);
        }
        CP_COMMIT();
    }

    const int NK = K / 64;  // 64
    for (int kt = 0; kt < NK; kt++) {
        const int s = kt & 1;
        CP_WAIT1();
        __syncthreads();

        const uint32_t aB = aF0 + (uint32_t)(s * G_ST * 2);
        const uint32_t bB = bF0 + (uint32_t)(s * G_ST * 2);
#pragma unroll
        for (int kk = 0; kk < 64; kk += 16) {
            uint32_t af[2][4], bf[4][4];
#pragma unroll
            for (int mt = 0; mt < 2; mt++)
                ldsm4(af[mt], aB + (mt * 16 * GP + kk) * 2);
#pragma unroll
            for (int p = 0; p < 4; p++)
                ldsm4(bf[p], bB + (p * 16 * GP + kk) * 2);
#pragma unroll
            for (int mt = 0; mt < 2; mt++)
#pragma unroll
                for (int nt = 0; nt < 8; nt++)
                    mma_16816(c[mt][nt], af[mt], &bf[nt >> 1][(nt & 1) * 2]);
        }
        __syncthreads();

        if (kt + 2 < NK) {
            const int ko = (kt + 2) * 64;
#pragma unroll
            for (int j = 0; j < 4; j++) {
                cp16(aD[j] + (uint32_t)(s * G_ST * 2), Ag[j] + ko);
                cp16(bD[j] + (uint32_t)(s * G_ST * 2), Bg[j] + ko);
            }
        }
        CP_COMMIT();
    }

    // ---- epilogue ----
    if (mode == 3) {
#pragma unroll
        for (int nt = 0; nt < 8; nt++) {
            const int col = n0 + wn + nt * 8 + t2;
            const float s0 = __ldg(scale + col), s1 = __ldg(scale + col + 1);
#pragma unroll
            for (int mt = 0; mt < 2; mt++) {
                const int row = m0 + wm + mt * 16 + gid;
                C[(size_t)row * DIM + col]           = c[mt][nt][0] * s0;
                C[(size_t)row * DIM + col + 1]       = c[mt][nt][1] * s1;
                C[(size_t)(row + 8) * DIM + col]     = c[mt][nt][2] * s0;
                C[(size_t)(row + 8) * DIM + col + 1] = c[mt][nt][3] * s1;
            }
        }
        return;
    }

    const int row0 = m0 + wm + gid;
#pragma unroll
    for (int mt = 0; mt < 2; mt++) {
#pragma unroll
        for (int half = 0; half < 2; half++) {
            const int row = row0 + mt * 16 + half * 8;
            const int sq = row & 511, b = row >> 9;
            __half* outH;
            float* cacheRow = nullptr;
            if (mode == 0) {
                outH = g_qh + (size_t)row * DIM;
            } else if (mode == 1) {
                outH = g_kh + (size_t)row * DIM;
                cacheRow = C + ((size_t)(b * MAXSEQ + __ldg(idx + sq))) * DIM;
            } else {
                outH = g_vh + (size_t)row * DIM;
                cacheRow = C + ((size_t)(b * MAXSEQ + __ldg(idx + sq))) * DIM;
            }
#pragma unroll
            for (int nt = 0; nt < 8; nt++) {
                const int col = n0 + wn + nt * 8 + t2;
                const float s0 = __ldg(scale + col), s1 = __ldg(scale + col + 1);
                const float v0 = c[mt][nt][half * 2]     * s0;
                const float v1 = c[mt][nt][half * 2 + 1] * s1;
                if (mode == 2) {
                    *(uint32_t*)(outH + col) = pack2f(v0, v1);
                    float2 f2; f2.x = v0; f2.y = v1;
                    *(float2*)(cacheRow + col) = f2;
                } else {
                    const int p = (col & 127) >> 1;
                    const float cv = __ldg(fcos + sq * 64 + p);
                    const float sv = __ldg(fsin + sq * 64 + p);
                    const float r0 = v0 * cv - v1 * sv;
                    const float r1 = v0 * sv + v1 * cv;
                    if (mode == 0) {
                        *(uint32_t*)(outH + col) = pack2f(r0 * QK_SCALE, r1 * QK_SCALE);
                    } else {
                        *(uint32_t*)(outH + col) = pack2f(r0, r1);
                        float2 f2; f2.x = r0; f2.y = r1;
                        *(float2*)(cacheRow + col) = f2;
                    }
                }
            }
        }
    }
}

// =====================================================================
// prep kernel: y=0 wq int32->fp16; y=1 x fp32->fp16
// (wk/wv conversions ride the Q-GEMM launch; wo rides the flash launch)
// =====================================================================
__global__ void prep_kernel(const int4* __restrict__ wq, __half* __restrict__ wqOut,
                            const float4* __restrict__ x, __half* __restrict__ xout,
                            int wN4, int xN4)
{
    if (blockIdx.y == 0) {
        for (int i = blockIdx.x * blockDim.x + threadIdx.x; i < wN4; i += gridDim.x * blockDim.x) {
            const int4 v = wq[i];
            __half2 h0 = __halves2half2(__int2half_rn(v.x), __int2half_rn(v.y));
            __half2 h1 = __halves2half2(__int2half_rn(v.z), __int2half_rn(v.w));
            uint2 u;
            u.x = *reinterpret_cast<uint32_t*>(&h0);
            u.y = *reinterpret_cast<uint32_t*>(&h1);
            ((uint2*)wqOut)[i] = u;
        }
    } else {
        for (int i = blockIdx.x * blockDim.x + threadIdx.x; i < xN4; i += gridDim.x * blockDim.x) {
            const float4 v = x[i];
            __half2 h0 = __floats2half2_rn(v.x, v.y);
            __half2 h1 = __floats2half2_rn(v.z, v.w);
            uint2 u;
            u.x = *reinterpret_cast<uint32_t*>(&h0);
            u.y = *reinterpret_cast<uint32_t*>(&h1);
            ((uint2*)xout)[i] = u;
        }
    }
}

// =====================================================================
// Flash attention. grid (128, 6): y in [0,4) attention (qt = 3-y, LPT),
// y in [4,6) = wo int32->fp16 conversion filler blocks.
// =====================================================================
constexpr int FP = 136;
constexpr int F_TILE = 128 * FP;
constexpr int F_SMEM = 5 * F_TILE * 2;

__global__ __launch_bounds__(256) void flash_kernel(
    const int4* __restrict__ woSrc, __half* __restrict__ woDst, int wN4)
{
    if (blockIdx.y >= 4) {
        const int bid = (blockIdx.y - 4) * gridDim.x + blockIdx.x;  // 0..255
        for (int i = bid * 256 + threadIdx.x; i < wN4; i += 256 * 256) {
            const int4 v = woSrc[i];
            __half2 h0 = __halves2half2(__int2half_rn(v.x), __int2half_rn(v.y));
            __half2 h1 = __halves2half2(__int2half_rn(v.z), __int2half_rn(v.w));
            uint2 u;
            u.x = *reinterpret_cast<uint32_t*>(&h0);
            u.y = *reinterpret_cast<uint32_t*>(&h1);
            ((uint2*)woDst)[i] = u;
        }
        return;
    }

    extern __shared__ __half sm[];
    __half* Qs = sm;
    __half* Ks = sm + F_TILE;
    __half* Vs = sm + 3 * F_TILE;

    const int qt = 3 - blockIdx.y;    // LPT: heaviest tiles first
    const int z  = blockIdx.x;
    const int b = z >> 5, h = z & 31;
    const int tid = threadIdx.x, warp = tid >> 5, lane = tid & 31;
    const int gid = lane >> 2, t2 = (lane & 3) * 2;

    const __half* Qg = g_qh + ((size_t)(b * SEQ + qt * 128)) * DIM + h * HD;
    const __half* Kg = g_kh + ((size_t)b * SEQ) * DIM + h * HD;
    const __half* Vg = g_vh + ((size_t)b * SEQ) * DIM + h * HD;

#pragma unroll
    for (int j = 0; j < 8; j++) {
        const int c = tid + j * 256;
        const int row = c >> 4, sub = (c & 15) * 8;
        cp16(smem_u32(Qs + row * FP + sub), Qg + (size_t)row * DIM + sub);
    }
    CP_COMMIT();
#pragma unroll
    for (int j = 0; j < 8; j++) {
        const int c = tid + j * 256;
        const int row = c >> 4, sub = (c & 15) * 8;
        cp16(smem_u32(Ks + row * FP + sub), Kg + (size_t)row * DIM + sub);
        cp16(smem_u32(Vs + row * FP + sub), Vg + (size_t)row * DIM + sub);
    }
    CP_COMMIT();
    CP_WAIT0();
    __syncthreads();

    const int fr = (lane & 7) + ((lane >> 3) & 1) * 8;
    const int fc = ((lane >> 4) & 1) * 8;
    const int kb_r = (lane & 7) + ((lane >> 4) & 1) * 8;
    const int kb_c = ((lane >> 3) & 1) * 8;

    const uint32_t qB = smem_u32(Qs + (warp * 16 + fr) * FP + fc);

    float o[16][4];
#pragma unroll
    for (int nt = 0; nt < 16; nt++)
#pragma unroll
        for (int r = 0; r < 4; r++) o[nt][r] = 0.f;
    float m0 = -1e30f, m1 = -1e30f, l0 = 0.f, l1 = 0.f;

    for (int kt = 0; kt <= qt; kt++) {
        const int buf = kt & 1;

        if (kt < qt) {
            const __half* Kn = Kg + (size_t)(kt + 1) * 128 * DIM;
            const __half* Vn = Vg + (size_t)(kt + 1) * 128 * DIM;
            __half* Kd = Ks + (buf ^ 1) * F_TILE;
            __half* Vd = Vs + (buf ^ 1) * F_TILE;
#pragma unroll
            for (int j = 0; j < 8; j++) {
                const int c = tid + j * 256;
                const int row = c >> 4, sub = (c & 15) * 8;
                cp16(smem_u32(Kd + row * FP + sub), Kn + (size_t)row * DIM + sub);
                cp16(smem_u32(Vd + row * FP + sub), Vn + (size_t)row * DIM + sub);
            }
            CP_COMMIT();
        }

        const uint32_t kB = smem_u32(Ks + buf * F_TILE + kb_r * FP + kb_c);
        const uint32_t vB = smem_u32(Vs + buf * F_TILE + fr * FP + fc);

        float s[16][4];
#pragma unroll
        for (int nt = 0; nt < 16; nt++)
#pragma unroll
            for (int r = 0; r < 4; r++) s[nt][r] = 0.f;

#pragma unroll
        for (int kk = 0; kk < 8; kk++) {
            uint32_t a[4];
            ldsm4(a, qB + kk * 32);
#pragma unroll
            for (int p = 0; p < 8; p++) {
                uint32_t bk[4];
                ldsm4(bk, kB + (p * 16 * FP + kk * 16) * 2);
                mma_16816(s[2 * p],     a, bk);
                mma_16816(s[2 * p + 1], a, bk + 2);
            }
        }

        if (kt == qt) {
            const int r0 = warp * 16 + gid, r1 = r0 + 8;
#pragma unroll
            for (int nt = 0; nt < 16; nt++) {
                const int c0 = nt * 8 + t2;
                if (c0 > r0)     s[nt][0] = -1e30f;
                if (c0 + 1 > r0) s[nt][1] = -1e30f;
                if (c0 > r1)     s[nt][2] = -1e30f;
                if (c0 + 1 > r1) s[nt][3] = -1e30f;
            }
        }

        float mx0 = -1e30f, mx1 = -1e30f;
#pragma unroll
        for (int nt = 0; nt < 16; nt++) {
            mx0 = fmaxf(mx0, fmaxf(s[nt][0], s[nt][1]));
            mx1 = fmaxf(mx1, fmaxf(s[nt][2], s[nt][3]));
        }
        mx0 = fmaxf(mx0, __shfl_xor_sync(0xffffffffu, mx0, 1));
        mx0 = fmaxf(mx0, __shfl_xor_sync(0xffffffffu, mx0, 2));
        mx1 = fmaxf(mx1, __shfl_xor_sync(0xffffffffu, mx1, 1));
        mx1 = fmaxf(mx1, __shfl_xor_sync(0xffffffffu, mx1, 2));

        const float mn0 = fmaxf(m0, mx0), mn1 = fmaxf(m1, mx1);
        const float sc0 = __expf(m0 - mn0), sc1 = __expf(m1 - mn1);
        m0 = mn0; m1 = mn1;

        float sum0 = 0.f, sum1 = 0.f;
#pragma unroll
        for (int nt = 0; nt < 16; nt++) {
            s[nt][0] = __expf(s[nt][0] - mn0);
            s[nt][1] = __expf(s[nt][1] - mn0);
            s[nt][2] = __expf(s[nt][2] - mn1);
            s[nt][3] = __expf(s[nt][3] - mn1);
            sum0 += s[nt][0] + s[nt][1];
            sum1 += s[nt][2] + s[nt][3];
        }
        sum0 += __shfl_xor_sync(0xffffffffu, sum0, 1);
        sum0 += __shfl_xor_sync(0xffffffffu, sum0, 2);
        sum1 += __shfl_xor_sync(0xffffffffu, sum1, 1);
        sum1 += __shfl_xor_sync(0xffffffffu, sum1, 2);
        l0 = l0 * sc0 + sum0;
        l1 = l1 * sc1 + sum1;

#pragma unroll
        for (int nt = 0; nt < 16; nt++) {
            o[nt][0] *= sc0; o[nt][1] *= sc0;
            o[nt][2] *= sc1; o[nt][3] *= sc1;
        }

#pragma unroll
        for (int ks = 0; ks < 8; ks++) {
            uint32_t pa[4];
            pa[0] = pack2f(s[2 * ks][0],     s[2 * ks][1]);
            pa[1] = pack2f(s[2 * ks][2],     s[2 * ks][3]);
            pa[2] = pack2f(s[2 * ks + 1][0], s[2 * ks + 1][1]);
            pa[3] = pack2f(s[2 * ks + 1][2], s[2 * ks + 1][3]);
#pragma unroll
            for (int dp = 0; dp < 8; dp++) {
                uint32_t vb[4];
                ldsm4t(vb, vB + (ks * 16 * FP + dp * 16) * 2);
                mma_16816(o[2 * dp],     pa, vb);
                mma_16816(o[2 * dp + 1], pa, vb + 2);
            }
        }

        if (kt < qt) {
            CP_WAIT0();
            __syncthreads();
        }
    }

    const float i0 = 1.f / l0, i1 = 1.f / l1;
    const int r0 = qt * 128 + warp * 16 + gid;
    __half* O0 = g_attnh + (size_t)(b * SEQ + r0) * DIM + h * HD;
    __half* O1 = O0 + (size_t)8 * DIM;
#pragma unroll
    for (int nt = 0; nt < 16; nt++) {
        const int col = nt * 8 + t2;
        *(uint32_t*)(O0 + col) = pack2f(o[nt][0] * i0, o[nt][1] * i0);
        *(uint32_t*)(O1 + col) = pack2f(o[nt][2] * i1, o[nt][3] * i1);
    }
}

// =====================================================================
extern "C" void kernel_launch(void* const* d_in, const int* in_sizes, int n_in,
                              void* d_out, int out_size)
{
    (void)in_sizes; (void)n_in; (void)out_size;
    const float* x    = (const float*)d_in[0];
    const float* fcos = (const float*)d_in[1];
    const float* fsin = (const float*)d_in[2];
    const int*   idx  = (const int*)d_in[4];
    const int*   wq   = (const int*)d_in[7];
    const float* sq   = (const float*)d_in[8];
    const int*   wk   = (const int*)d_in[9];
    const float* sk   = (const float*)d_in[10];
    const int*   wv   = (const int*)d_in[11];
    const float* sv   = (const float*)d_in[12];
    const int*   wo   = (const int*)d_in[13];
    const float* so   = (const float*)d_in[14];

    float* out    = (float*)d_out;
    float* cacheK = out + (size_t)BSZ * SEQ * DIM;
    float* cacheV = cacheK + (size_t)BSZ * MAXSEQ * NHEADS * HD;

    __half *pxh = nullptr, *pwh = nullptr, *pah = nullptr;
    cudaGetSymbolAddress((void**)&pxh, g_xh);
    cudaGetSymbolAddress((void**)&pwh, g_wh);
    cudaGetSymbolAddress((void**)&pah, g_attnh);

    cudaFuncSetAttribute(gemm128, cudaFuncAttributeMaxDynamicSharedMemorySize, G_SMEM);
    cudaFuncSetAttribute(flash_kernel, cudaFuncAttributeMaxDynamicSharedMemorySize, F_SMEM);

    const size_t W = (size_t)DIM * DIM;
    const int wN4 = (int)(W / 4);

    // 1) minimal prep: wq + x only
    prep_kernel<<<dim3(1184, 2), 256>>>((const int4*)wq, pwh + 0 * W,
                                        (const float4*)x, pxh,
                                        wN4, (int)(BSZ * SEQ * DIM / 4));

    // 2) Q projection (+RoPE) with fillers: wk/wv conversion + cache-tail zero
    GemmSet g1;
    g1.B[0] = pwh + 0 * W; g1.s[0] = sq; g1.C[0] = nullptr; g1.mode[0] = 0;
    g1.B[1] = nullptr;     g1.s[1] = nullptr; g1.C[1] = nullptr; g1.mode[1] = 3;
    g1.nGemm = 1; g1.nConv = 2;
    g1.cw[0] = (const int4*)wk; g1.cwo[0] = pwh + 1 * W;
    g1.cw[1] = (const int4*)wv; g1.cwo[1] = pwh + 2 * W;
    g1.wN4 = wN4; g1.zk = cacheK; g1.zv = cacheV;
    gemm128<<<dim3(DIM / 128, (BSZ * SEQ) / 128, 4), 256, G_SMEM>>>(pxh, g1, fcos, fsin, idx);

    // 3) K + V projections (+RoPE/cache scatter)
    GemmSet g2;
    g2.B[0] = pwh + 1 * W; g2.s[0] = sk; g2.C[0] = cacheK; g2.mode[0] = 1;
    g2.B[1] = pwh + 2 * W; g2.s[1] = sv; g2.C[1] = cacheV; g2.mode[1] = 2;
    g2.nGemm = 2; g2.nConv = 0;
    g2.cw[0] = nullptr; g2.cwo[0] = nullptr;
    g2.cw[1] = nullptr; g2.cwo[1] = nullptr;
    g2.wN4 = wN4; g2.zk = cacheK; g2.zv = cacheV;
    gemm128<<<dim3(DIM / 128, (BSZ * SEQ) / 128, 2), 256, G_SMEM>>>(pxh, g2, fcos, fsin, idx);

    // 4) fused flash attention (heavy tiles first) + wo-conversion filler
    flash_kernel<<<dim3(BSZ * NHEADS, 6), 256, F_SMEM>>>(
        (const int4*)wo, pwh + 3 * W, wN4);

    // 5) output projection
    GemmSet g3;
    g3.B[0] = pwh + 3 * W; g3.s[0] = so; g3.C[0] = out; g3.mode[0] = 3;
    g3.B[1] = nullptr;     g3.s[1] = nullptr; g3.C[1] = nullptr; g3.mode[1] = 3;
    g3.nGemm = 1; g3.nConv = 0;
    g3.cw[0] = nullptr; g3.cwo[0] = nullptr;
    g3.cw[1] = nullptr; g3.cwo[1] = nullptr;
    g3.wN4 = wN4; g3.zk = cacheK; g3.zv = cacheV;
    gemm128<<<dim3(DIM / 128, (BSZ * SEQ) / 128, 1), 256, G_SMEM>>>(pah, g3, fcos, fsin, idx);
}

// round 16
// speedup vs baseline: 1.1628x; 1.0416x over previous
#include <cuda_runtime.h>
#include <cuda_fp16.h>
#include <stdint.h>

#define DIM 4096
#define NHEADS 32
#define HD 128
#define BSZ 4
#define SEQ 512
#define MAXSEQ 2048

// ---------------- scratch ----------------
static __device__ __align__(256) __half g_xh[(size_t)BSZ * SEQ * DIM];
static __device__ __align__(256) __half g_attnh[(size_t)BSZ * SEQ * DIM];
static __device__ __align__(256) __half g_wh[(size_t)4 * DIM * DIM];
static __device__ __align__(256) __half g_qh[(size_t)BSZ * SEQ * DIM];
static __device__ __align__(256) __half g_kh[(size_t)BSZ * SEQ * DIM];
static __device__ __align__(256) __half g_vh[(size_t)BSZ * SEQ * DIM];

// ---------------- helpers ----------------
__device__ __forceinline__ uint32_t smem_u32(const void* p) {
    uint32_t r;
    asm("{ .reg .u64 t; cvta.to.shared.u64 t, %1; cvt.u32.u64 %0, t; }" : "=r"(r) : "l"(p));
    return r;
}

__device__ __forceinline__ void cp16(uint32_t d, const void* g) {
    asm volatile("cp.async.cg.shared.global [%0], [%1], 16;" :: "r"(d), "l"(g) : "memory");
}
#define CP_COMMIT() asm volatile("cp.async.commit_group;" ::: "memory")
#define CP_WAIT1()  asm volatile("cp.async.wait_group 1;" ::: "memory")
#define CP_WAIT0()  asm volatile("cp.async.wait_group 0;" ::: "memory")

__device__ __forceinline__ void ldsm4(uint32_t* r, uint32_t a) {
    asm volatile("ldmatrix.sync.aligned.m8n8.x4.shared.b16 {%0,%1,%2,%3}, [%4];"
                 : "=r"(r[0]), "=r"(r[1]), "=r"(r[2]), "=r"(r[3]) : "r"(a));
}
__device__ __forceinline__ void ldsm4t(uint32_t* r, uint32_t a) {
    asm volatile("ldmatrix.sync.aligned.m8n8.x4.trans.shared.b16 {%0,%1,%2,%3}, [%4];"
                 : "=r"(r[0]), "=r"(r[1]), "=r"(r[2]), "=r"(r[3]) : "r"(a));
}

__device__ __forceinline__ void mma_16816(float* c, const uint32_t* a, const uint32_t* b) {
    asm volatile(
        "mma.sync.aligned.m16n8k16.row.col.f32.f16.f16.f32 "
        "{%0,%1,%2,%3}, {%4,%5,%6,%7}, {%8,%9}, {%0,%1,%2,%3};\n"
        : "+f"(c[0]), "+f"(c[1]), "+f"(c[2]), "+f"(c[3])
        : "r"(a[0]), "r"(a[1]), "r"(a[2]), "r"(a[3]),
          "r"(b[0]), "r"(b[1]));
}

__device__ __forceinline__ uint32_t pack2f(float a, float b) {
    __half2 t = __floats2half2_rn(a, b);
    return *reinterpret_cast<uint32_t*>(&t);
}

constexpr float QK_SCALE = 0.08838834764831845f;  // 1/sqrt(128)

// =====================================================================
//  gemm128: CTA tile 128x128, 256 threads, warp tile 32x64, BK=64,
//  2-stage cp.async ring, 2 CTAs/SM  (proven round-12 mainloop).
//  Epilogue mode: 0=Q(rope->fp16 qh), 1=K(rope->fp16 kh + fp32 cacheK),
//                 2=V(fp16 vh + fp32 cacheV), 3=plain fp32 C.
//  blockIdx.z == 3 (QKV launch only): filler blocks —
//    bid < 256  : wo int32 -> fp16 conversion
//    bid >= 256 : cache-tail zeroing
// =====================================================================
constexpr int GP = 72;                       // smem pitch (halves)
constexpr int G_ST = 128 * GP;               // per-matrix stage halves
constexpr int G_SMEM = 2 * 2 * G_ST * 2;     // 73728 bytes

struct GemmSet {
    const __half* B[3];
    const float*  s[3];
    float*        C[3];      // mode 3: output; modes 1/2: cache base
    int           mode[3];
    const int4*   woSrc;     // filler conversion source
    __half*       woDst;     // filler conversion dest
    int           wN4;
};

__global__ void __launch_bounds__(256, 2) gemm128(
    const __half* __restrict__ A, GemmSet gs,
    const float* __restrict__ fcos, const float* __restrict__ fsin,
    const int* __restrict__ idx)
{
    // ---- filler blocks ----
    if (blockIdx.z == 3) {
        const int bid = blockIdx.y * gridDim.x + blockIdx.x;   // 0..511
        if (bid < 256) {
            // convert wo int32 -> fp16 (rides the tensor-bound launch's idle DRAM)
            const int4* w = gs.woSrc;
            __half* o = gs.woDst;
            for (int i = bid * 256 + threadIdx.x; i < gs.wN4; i += 256 * 256) {
                const int4 v = w[i];
                __half2 h0 = __halves2half2(__int2half_rn(v.x), __int2half_rn(v.y));
                __half2 h1 = __halves2half2(__int2half_rn(v.z), __int2half_rn(v.w));
                uint2 u;
                u.x = *reinterpret_cast<uint32_t*>(&h0);
                u.y = *reinterpret_cast<uint32_t*>(&h1);
                ((uint2*)o)[i] = u;
            }
        } else {
            // zero cache tails (rows 512..2047 of both caches)
            float4* ck = (float4*)gs.C[1];
            float4* cv = (float4*)gs.C[2];
            const int perB = 1536 * 1024;
            const int n = BSZ * perB;
            const float4 z4 = make_float4(0.f, 0.f, 0.f, 0.f);
            for (int i = (bid - 256) * 256 + threadIdx.x; i < n; i += 256 * 256) {
                const int b = i / perB, r = i - b * perB;
                const size_t off = ((size_t)b * MAXSEQ + SEQ) * (DIM / 4) + r;
                ck[off] = z4;
                cv[off] = z4;
            }
        }
        return;
    }

    extern __shared__ __half sm[];
    __half* As = sm;                 // [2][128][72]
    __half* Bs = sm + 2 * G_ST;      // [2][128][72]

    const __half* Bw = gs.B[blockIdx.z];
    const float*  scale = gs.s[blockIdx.z];
    float*        C = gs.C[blockIdx.z];
    const int     mode = gs.mode[blockIdx.z];

    const int K = DIM;
    const int tid = threadIdx.x;
    const int warp = tid >> 5, lane = tid & 31;
    const int m0 = blockIdx.y * 128, n0 = blockIdx.x * 128;
    const int wm = (warp & 3) * 32, wn = (warp >> 2) * 64;
    const int gid = lane >> 2, t2 = (lane & 3) * 2;

    // ---- loaders ----
    uint32_t aD[4], bD[4];
    const __half *Ag[4], *Bg[4];
#pragma unroll
    for (int j = 0; j < 4; j++) {
        const int id = tid + j * 256;
        const int row = id >> 3, sub = (id & 7) * 8;
        aD[j] = smem_u32(As + row * GP + sub);
        bD[j] = smem_u32(Bs + row * GP + sub);
        Ag[j] = A + (size_t)(m0 + row) * K + sub;
        Bg[j] = Bw + (size_t)(n0 + row) * K + sub;
    }

    // ---- fragment lane addressing ----
    const int a_r = (lane & 7) + ((lane >> 3) & 1) * 8;
    const int a_c = ((lane >> 4) & 1) * 8;
    const int b_r = (lane & 7) + ((lane >> 4) & 1) * 8;
    const int b_c = ((lane >> 3) & 1) * 8;
    const uint32_t aF0 = smem_u32(As + (wm + a_r) * GP + a_c);
    const uint32_t bF0 = smem_u32(Bs + (wn + b_r) * GP + b_c);

    float c[2][8][4];
#pragma unroll
    for (int mt = 0; mt < 2; mt++)
#pragma unroll
        for (int nt = 0; nt < 8; nt++)
#pragma unroll
            for (int r = 0; r < 4; r++) c[mt][nt][r] = 0.f;

    // ---- prologue ----
#pragma unroll
    for (int s = 0; s < 2; s++) {
#pragma unroll
        for (int j = 0; j < 4; j++) {
            cp16(aD[j] + (uint32_t)(s * G_ST * 2), Ag[j] + s * 64);
            cp16(bD[j] + (uint32_t)(s * G_ST * 2), Bg[j] + s * 64);
        }
        CP_COMMIT();
    }

    const int NK = K / 64;  // 64
    for (int kt = 0; kt < NK; kt++) {
        const int s = kt & 1;
        CP_WAIT1();
        __syncthreads();

        const uint32_t aB = aF0 + (uint32_t)(s * G_ST * 2);
        const uint32_t bB = bF0 + (uint32_t)(s * G_ST * 2);
#pragma unroll
        for (int kk = 0; kk < 64; kk += 16) {
            uint32_t af[2][4], bf[4][4];
#pragma unroll
            for (int mt = 0; mt < 2; mt++)
                ldsm4(af[mt], aB + (mt * 16 * GP + kk) * 2);
#pragma unroll
            for (int p = 0; p < 4; p++)
                ldsm4(bf[p], bB + (p * 16 * GP + kk) * 2);
#pragma unroll
            for (int mt = 0; mt < 2; mt++)
#pragma unroll
                for (int nt = 0; nt < 8; nt++)
                    mma_16816(c[mt][nt], af[mt], &bf[nt >> 1][(nt & 1) * 2]);
        }
        __syncthreads();

        if (kt + 2 < NK) {
            const int ko = (kt + 2) * 64;
#pragma unroll
            for (int j = 0; j < 4; j++) {
                cp16(aD[j] + (uint32_t)(s * G_ST * 2), Ag[j] + ko);
                cp16(bD[j] + (uint32_t)(s * G_ST * 2), Bg[j] + ko);
            }
        }
        CP_COMMIT();
    }

    // ---- epilogue ----
    if (mode == 3) {
#pragma unroll
        for (int nt = 0; nt < 8; nt++) {
            const int col = n0 + wn + nt * 8 + t2;
            const float s0 = __ldg(scale + col), s1 = __ldg(scale + col + 1);
#pragma unroll
            for (int mt = 0; mt < 2; mt++) {
                const int row = m0 + wm + mt * 16 + gid;
                C[(size_t)row * DIM + col]           = c[mt][nt][0] * s0;
                C[(size_t)row * DIM + col + 1]       = c[mt][nt][1] * s1;
                C[(size_t)(row + 8) * DIM + col]     = c[mt][nt][2] * s0;
                C[(size_t)(row + 8) * DIM + col + 1] = c[mt][nt][3] * s1;
            }
        }
        return;
    }

    const int row0 = m0 + wm + gid;
#pragma unroll
    for (int mt = 0; mt < 2; mt++) {
#pragma unroll
        for (int half = 0; half < 2; half++) {
            const int row = row0 + mt * 16 + half * 8;
            const int sq = row & 511, b = row >> 9;
            __half* outH;
            float* cacheRow = nullptr;
            if (mode == 0) {
                outH = g_qh + (size_t)row * DIM;
            } else if (mode == 1) {
                outH = g_kh + (size_t)row * DIM;
                cacheRow = C + ((size_t)(b * MAXSEQ + __ldg(idx + sq))) * DIM;
            } else {
                outH = g_vh + (size_t)row * DIM;
                cacheRow = C + ((size_t)(b * MAXSEQ + __ldg(idx + sq))) * DIM;
            }
#pragma unroll
            for (int nt = 0; nt < 8; nt++) {
                const int col = n0 + wn + nt * 8 + t2;
                const float s0 = __ldg(scale + col), s1 = __ldg(scale + col + 1);
                const float v0 = c[mt][nt][half * 2]     * s0;
                const float v1 = c[mt][nt][half * 2 + 1] * s1;
                if (mode == 2) {
                    *(uint32_t*)(outH + col) = pack2f(v0, v1);
                    float2 f2; f2.x = v0; f2.y = v1;
                    *(float2*)(cacheRow + col) = f2;
                } else {
                    const int p = (col & 127) >> 1;
                    const float cv = __ldg(fcos + sq * 64 + p);
                    const float sv = __ldg(fsin + sq * 64 + p);
                    const float r0 = v0 * cv - v1 * sv;
                    const float r1 = v0 * sv + v1 * cv;
                    if (mode == 0) {
                        *(uint32_t*)(outH + col) = pack2f(r0 * QK_SCALE, r1 * QK_SCALE);
                    } else {
                        *(uint32_t*)(outH + col) = pack2f(r0, r1);
                        float2 f2; f2.x = r0; f2.y = r1;
                        *(float2*)(cacheRow + col) = f2;
                    }
                }
            }
        }
    }
}

// =====================================================================
// prep kernel: y=0..2 weights wq/wk/wv int32->fp16; y=3 x fp32->fp16
// (wo conversion rides the QKV launch's idle DRAM slack)
// =====================================================================
struct WSet { const int4* w[3]; __half* o[3]; };

__global__ void prep_kernel(WSet ws, const float4* __restrict__ x,
                            __half* __restrict__ xout, int wN4, int xN4)
{
    if (blockIdx.y < 3) {
        const int4* w = ws.w[blockIdx.y];
        __half* out = ws.o[blockIdx.y];
        for (int i = blockIdx.x * blockDim.x + threadIdx.x; i < wN4; i += gridDim.x * blockDim.x) {
            const int4 v = w[i];
            __half2 h0 = __halves2half2(__int2half_rn(v.x), __int2half_rn(v.y));
            __half2 h1 = __halves2half2(__int2half_rn(v.z), __int2half_rn(v.w));
            uint2 u;
            u.x = *reinterpret_cast<uint32_t*>(&h0);
            u.y = *reinterpret_cast<uint32_t*>(&h1);
            ((uint2*)out)[i] = u;
        }
    } else {
        for (int i = blockIdx.x * blockDim.x + threadIdx.x; i < xN4; i += gridDim.x * blockDim.x) {
            const float4 v = x[i];
            __half2 h0 = __floats2half2_rn(v.x, v.y);
            __half2 h1 = __floats2half2_rn(v.z, v.w);
            uint2 u;
            u.x = *reinterpret_cast<uint32_t*>(&h0);
            u.y = *reinterpret_cast<uint32_t*>(&h1);
            ((uint2*)xout)[i] = u;
        }
    }
}

// =====================================================================
// Flash attention (plain; grid (128,4), qt = 3 - y for LPT scheduling)
// =====================================================================
constexpr int FP = 136;
constexpr int F_TILE = 128 * FP;
constexpr int F_SMEM = 5 * F_TILE * 2;

__global__ __launch_bounds__(256) void flash_kernel()
{
    extern __shared__ __half sm[];
    __half* Qs = sm;
    __half* Ks = sm + F_TILE;
    __half* Vs = sm + 3 * F_TILE;

    const int qt = 3 - blockIdx.y;    // LPT: heaviest tiles first
    const int z  = blockIdx.x;
    const int b = z >> 5, h = z & 31;
    const int tid = threadIdx.x, warp = tid >> 5, lane = tid & 31;
    const int gid = lane >> 2, t2 = (lane & 3) * 2;

    const __half* Qg = g_qh + ((size_t)(b * SEQ + qt * 128)) * DIM + h * HD;
    const __half* Kg = g_kh + ((size_t)b * SEQ) * DIM + h * HD;
    const __half* Vg = g_vh + ((size_t)b * SEQ) * DIM + h * HD;

#pragma unroll
    for (int j = 0; j < 8; j++) {
        const int c = tid + j * 256;
        const int row = c >> 4, sub = (c & 15) * 8;
        cp16(smem_u32(Qs + row * FP + sub), Qg + (size_t)row * DIM + sub);
    }
    CP_COMMIT();
#pragma unroll
    for (int j = 0; j < 8; j++) {
        const int c = tid + j * 256;
        const int row = c >> 4, sub = (c & 15) * 8;
        cp16(smem_u32(Ks + row * FP + sub), Kg + (size_t)row * DIM + sub);
        cp16(smem_u32(Vs + row * FP + sub), Vg + (size_t)row * DIM + sub);
    }
    CP_COMMIT();
    CP_WAIT0();
    __syncthreads();

    const int fr = (lane & 7) + ((lane >> 3) & 1) * 8;
    const int fc = ((lane >> 4) & 1) * 8;
    const int kb_r = (lane & 7) + ((lane >> 4) & 1) * 8;
    const int kb_c = ((lane >> 3) & 1) * 8;

    const uint32_t qB = smem_u32(Qs + (warp * 16 + fr) * FP + fc);

    float o[16][4];
#pragma unroll
    for (int nt = 0; nt < 16; nt++)
#pragma unroll
        for (int r = 0; r < 4; r++) o[nt][r] = 0.f;
    float m0 = -1e30f, m1 = -1e30f, l0 = 0.f, l1 = 0.f;

    for (int kt = 0; kt <= qt; kt++) {
        const int buf = kt & 1;

        if (kt < qt) {
            const __half* Kn = Kg + (size_t)(kt + 1) * 128 * DIM;
            const __half* Vn = Vg + (size_t)(kt + 1) * 128 * DIM;
            __half* Kd = Ks + (buf ^ 1) * F_TILE;
            __half* Vd = Vs + (buf ^ 1) * F_TILE;
#pragma unroll
            for (int j = 0; j < 8; j++) {
                const int c = tid + j * 256;
                const int row = c >> 4, sub = (c & 15) * 8;
                cp16(smem_u32(Kd + row * FP + sub), Kn + (size_t)row * DIM + sub);
                cp16(smem_u32(Vd + row * FP + sub), Vn + (size_t)row * DIM + sub);
            }
            CP_COMMIT();
        }

        const uint32_t kB = smem_u32(Ks + buf * F_TILE + kb_r * FP + kb_c);
        const uint32_t vB = smem_u32(Vs + buf * F_TILE + fr * FP + fc);

        float s[16][4];
#pragma unroll
        for (int nt = 0; nt < 16; nt++)
#pragma unroll
            for (int r = 0; r < 4; r++) s[nt][r] = 0.f;

#pragma unroll
        for (int kk = 0; kk < 8; kk++) {
            uint32_t a[4];
            ldsm4(a, qB + kk * 32);
#pragma unroll
            for (int p = 0; p < 8; p++) {
                uint32_t bk[4];
                ldsm4(bk, kB + (p * 16 * FP + kk * 16) * 2);
                mma_16816(s[2 * p],     a, bk);
                mma_16816(s[2 * p + 1], a, bk + 2);
            }
        }

        if (kt == qt) {
            const int r0 = warp * 16 + gid, r1 = r0 + 8;
#pragma unroll
            for (int nt = 0; nt < 16; nt++) {
                const int c0 = nt * 8 + t2;
                if (c0 > r0)     s[nt][0] = -1e30f;
                if (c0 + 1 > r0) s[nt][1] = -1e30f;
                if (c0 > r1)     s[nt][2] = -1e30f;
                if (c0 + 1 > r1) s[nt][3] = -1e30f;
            }
        }

        float mx0 = -1e30f, mx1 = -1e30f;
#pragma unroll
        for (int nt = 0; nt < 16; nt++) {
            mx0 = fmaxf(mx0, fmaxf(s[nt][0], s[nt][1]));
            mx1 = fmaxf(mx1, fmaxf(s[nt][2], s[nt][3]));
        }
        mx0 = fmaxf(mx0, __shfl_xor_sync(0xffffffffu, mx0, 1));
        mx0 = fmaxf(mx0, __shfl_xor_sync(0xffffffffu, mx0, 2));
        mx1 = fmaxf(mx1, __shfl_xor_sync(0xffffffffu, mx1, 1));
        mx1 = fmaxf(mx1, __shfl_xor_sync(0xffffffffu, mx1, 2));

        const float mn0 = fmaxf(m0, mx0), mn1 = fmaxf(m1, mx1);
        const float sc0 = __expf(m0 - mn0), sc1 = __expf(m1 - mn1);
        m0 = mn0; m1 = mn1;

        float sum0 = 0.f, sum1 = 0.f;
#pragma unroll
        for (int nt = 0; nt < 16; nt++) {
            s[nt][0] = __expf(s[nt][0] - mn0);
            s[nt][1] = __expf(s[nt][1] - mn0);
            s[nt][2] = __expf(s[nt][2] - mn1);
            s[nt][3] = __expf(s[nt][3] - mn1);
            sum0 += s[nt][0] + s[nt][1];
            sum1 += s[nt][2] + s[nt][3];
        }
        sum0 += __shfl_xor_sync(0xffffffffu, sum0, 1);
        sum0 += __shfl_xor_sync(0xffffffffu, sum0, 2);
        sum1 += __shfl_xor_sync(0xffffffffu, sum1, 1);
        sum1 += __shfl_xor_sync(0xffffffffu, sum1, 2);
        l0 = l0 * sc0 + sum0;
        l1 = l1 * sc1 + sum1;

#pragma unroll
        for (int nt = 0; nt < 16; nt++) {
            o[nt][0] *= sc0; o[nt][1] *= sc0;
            o[nt][2] *= sc1; o[nt][3] *= sc1;
        }

#pragma unroll
        for (int ks = 0; ks < 8; ks++) {
            uint32_t pa[4];
            pa[0] = pack2f(s[2 * ks][0],     s[2 * ks][1]);
            pa[1] = pack2f(s[2 * ks][2],     s[2 * ks][3]);
            pa[2] = pack2f(s[2 * ks + 1][0], s[2 * ks + 1][1]);
            pa[3] = pack2f(s[2 * ks + 1][2], s[2 * ks + 1][3]);
#pragma unroll
            for (int dp = 0; dp < 8; dp++) {
                uint32_t vb[4];
                ldsm4t(vb, vB + (ks * 16 * FP + dp * 16) * 2);
                mma_16816(o[2 * dp],     pa, vb);
                mma_16816(o[2 * dp + 1], pa, vb + 2);
            }
        }

        if (kt < qt) {
            CP_WAIT0();
            __syncthreads();
        }
    }

    const float i0 = 1.f / l0, i1 = 1.f / l1;
    const int r0 = qt * 128 + warp * 16 + gid;
    __half* O0 = g_attnh + (size_t)(b * SEQ + r0) * DIM + h * HD;
    __half* O1 = O0 + (size_t)8 * DIM;
#pragma unroll
    for (int nt = 0; nt < 16; nt++) {
        const int col = nt * 8 + t2;
        *(uint32_t*)(O0 + col) = pack2f(o[nt][0] * i0, o[nt][1] * i0);
        *(uint32_t*)(O1 + col) = pack2f(o[nt][2] * i1, o[nt][3] * i1);
    }
}

// =====================================================================
extern "C" void kernel_launch(void* const* d_in, const int* in_sizes, int n_in,
                              void* d_out, int out_size)
{
    (void)in_sizes; (void)n_in; (void)out_size;
    const float* x    = (const float*)d_in[0];
    const float* fcos = (const float*)d_in[1];
    const float* fsin = (const float*)d_in[2];
    const int*   idx  = (const int*)d_in[4];
    const int*   wq   = (const int*)d_in[7];
    const float* sq   = (const float*)d_in[8];
    const int*   wk   = (const int*)d_in[9];
    const float* sk   = (const float*)d_in[10];
    const int*   wv   = (const int*)d_in[11];
    const float* sv   = (const float*)d_in[12];
    const int*   wo   = (const int*)d_in[13];
    const float* so   = (const float*)d_in[14];

    float* out    = (float*)d_out;
    float* cacheK = out + (size_t)BSZ * SEQ * DIM;
    float* cacheV = cacheK + (size_t)BSZ * MAXSEQ * NHEADS * HD;

    __half *pxh = nullptr, *pwh = nullptr, *pah = nullptr;
    cudaGetSymbolAddress((void**)&pxh, g_xh);
    cudaGetSymbolAddress((void**)&pwh, g_wh);
    cudaGetSymbolAddress((void**)&pah, g_attnh);

    cudaFuncSetAttribute(gemm128, cudaFuncAttributeMaxDynamicSharedMemorySize, G_SMEM);
    cudaFuncSetAttribute(flash_kernel, cudaFuncAttributeMaxDynamicSharedMemorySize, F_SMEM);

    const size_t W = (size_t)DIM * DIM;
    const int wN4 = (int)(W / 4);

    // 1) conversions (wq, wk, wv, x) — wo rides the QKV launch
    WSet ws;
    ws.w[0] = (const int4*)wq; ws.o[0] = pwh + 0 * W;
    ws.w[1] = (const int4*)wk; ws.o[1] = pwh + 1 * W;
    ws.w[2] = (const int4*)wv; ws.o[2] = pwh + 2 * W;
    prep_kernel<<<dim3(1184, 4), 256>>>(ws, (const float4*)x, pxh,
                                        wN4, (int)(BSZ * SEQ * DIM / 4));

    // 2) fused QKV projection + RoPE + cache scatter;
    //    z=3 fillers: wo conversion (256 blocks) + cache-tail zero (256 blocks)
    GemmSet qkv;
    qkv.B[0] = pwh + 0 * W; qkv.s[0] = sq; qkv.C[0] = nullptr; qkv.mode[0] = 0;
    qkv.B[1] = pwh + 1 * W; qkv.s[1] = sk; qkv.C[1] = cacheK;  qkv.mode[1] = 1;
    qkv.B[2] = pwh + 2 * W; qkv.s[2] = sv; qkv.C[2] = cacheV;  qkv.mode[2] = 2;
    qkv.woSrc = (const int4*)wo; qkv.woDst = pwh + 3 * W; qkv.wN4 = wN4;
    gemm128<<<dim3(DIM / 128, (BSZ * SEQ) / 128, 4), 256, G_SMEM>>>(pxh, qkv, fcos, fsin, idx);

    // 3) fused flash attention (heavy tiles first)
    flash_kernel<<<dim3(BSZ * NHEADS, 4), 256, F_SMEM>>>();

    // 4) output projection
    GemmSet og;
    og.B[0] = pwh + 3 * W; og.s[0] = so; og.C[0] = out; og.mode[0] = 3;
    og.B[1] = og.B[0]; og.s[1] = og.s[0]; og.C[1] = og.C[0]; og.mode[1] = 3;
    og.B[2] = og.B[0]; og.s[2] = og.s[0]; og.C[2] = og.C[0]; og.mode[2] = 3;
    og.woSrc = nullptr; og.woDst = nullptr; og.wN4 = 0;
    gemm128<<<dim3(DIM / 128, (BSZ * SEQ) / 128, 1), 256, G_SMEM>>>(pah, og, fcos, fsin, idx);
}